// round 13
// baseline (speedup 1.0000x reference)
#include <cuda_runtime.h>
#include <cuda_bf16.h>

// ---------------------------------------------------------------------------
// mlp_forward_model_44495861187262
//
// restructured (segment_sum distributes over the linear layer):
//   aggH   = segment_sum(relu(x@W1a+b1a))            (pass 1: 5x64 per node)
//   agg    = aggH @ W1b + cnt*b1b                    (per graph)
//   G      = agg @ W2a[5:69] + b2a                   (per graph, b2a folded)
//   out    = relu(x@W2a[0:5] + G[batch]) @ W2b + b2b (pass 2)
//
// batch is int32 (JAX x64 disabled). edge_index is dead in the reference.
// Packed f32x2 FFMA throughout (no max.f32x2 on this ptxas — R9 fail).
//
// Pass2 history: shape tuning (256/512/128-thr blocks) all pinned issue at
// ~49% with 64-70 regs -> per-warp structure was the limiter. R13: channel-
// major loop with node-pair packing and PRE-DUPLICATED weights in smem
// (weights load directly as f32x2 operands, no dup movs) -> ~40 regs ->
// 5-6 blocks/SM for real latency hiding.
//
// k_zero eliminated: __device__ globals are zero-initialized at load;
// k_graph self-cleans aggH/cnt after consuming them (graph-replay safe).
// ---------------------------------------------------------------------------

#define N_GRAPHS 4096
#define HIDDEN   64
#define NODE_F   5
#define OUT_F    4

typedef unsigned long long ull;

// scratch (allocation-free rule: __device__ globals; zero-initialized at load,
// and k_graph re-zeroes aggH/cnt after each consume)
__device__ float g_aggH[N_GRAPHS * HIDDEN];
__device__ float g_cnt[N_GRAPHS];
__device__ float g_G[N_GRAPHS * HIDDEN];

// ---- f32x2 helpers ---------------------------------------------------------
__device__ __forceinline__ ull pk2(float lo, float hi) {
    ull r; asm("mov.b64 %0, {%1,%2};" : "=l"(r) : "f"(lo), "f"(hi)); return r;
}
__device__ __forceinline__ ull pkdup(float v) {
    ull r; asm("mov.b64 %0, {%1,%1};" : "=l"(r) : "f"(v)); return r;
}
__device__ __forceinline__ void upk2(ull v, float& lo, float& hi) {
    asm("mov.b64 {%0,%1}, %2;" : "=f"(lo), "=f"(hi) : "l"(v));
}
__device__ __forceinline__ void fma2(ull& d, ull a, ull b) {
    asm("fma.rn.f32x2 %0, %1, %2, %0;" : "+l"(d) : "l"(a), "l"(b));
}
__device__ __forceinline__ ull add2(ull a, ull b) {
    ull r; asm("add.rn.f32x2 %0, %1, %2;" : "=l"(r) : "l"(a), "l"(b)); return r;
}
__device__ __forceinline__ void relu2(ull& a) {
    float lo, hi; upk2(a, lo, hi);
    lo = fmaxf(lo, 0.0f); hi = fmaxf(hi, 0.0f);
    a = pk2(lo, hi);
}

// ---------------------------------------------------------------------------
// Pass 1: warp owns 64 contiguous nodes. Lane owns channels c0=lane, c1=lane+32.
// Nodes processed in PAIRS packed into f32x2 lanes: xp[k]=(x_n[k], x_{n+1}[k]);
// accumulators stay packed (halves summed only at flush). batch sorted =>
// graph id warp-uniform; atomic flush only at segment boundaries.
#define NPW 64

__global__ void k_pass1(const float* __restrict__ x,
                        const int* __restrict__ batch,
                        const float* __restrict__ W1a,
                        const float* __restrict__ b1a,
                        int N) {
    int warp = (blockIdx.x * blockDim.x + threadIdx.x) >> 5;
    int lane = threadIdx.x & 31;
    long long start = (long long)warp * NPW;
    if (start >= N) return;

    const int c0 = lane, c1 = lane + 32;

    float w0s[NODE_F], w1s[NODE_F];
    ull   w0d[NODE_F], w1d[NODE_F];
#pragma unroll
    for (int k = 0; k < NODE_F; k++) {
        w0s[k] = __ldg(W1a + k * HIDDEN + c0);
        w1s[k] = __ldg(W1a + k * HIDDEN + c1);
        w0d[k] = pkdup(w0s[k]);
        w1d[k] = pkdup(w1s[k]);
    }
    const float b0s = __ldg(b1a + c0);
    const float b1s = __ldg(b1a + c1);
    const ull   b0d = pkdup(b0s);
    const ull   b1d = pkdup(b1s);

    unsigned cur_g;
    {
        unsigned g = (unsigned)__ldg(batch + start);
        cur_g = (g < N_GRAPHS) ? g : 0u;
    }
    ull acc0 = 0, acc1 = 0;
    float cnt = 0.0f;

#define P1_FLUSH() do {                                            \
        float lo, hi;                                              \
        upk2(acc0, lo, hi);                                        \
        atomicAdd(&g_aggH[cur_g * HIDDEN + c0], lo + hi);          \
        upk2(acc1, lo, hi);                                        \
        atomicAdd(&g_aggH[cur_g * HIDDEN + c1], lo + hi);          \
        if (lane == 0) atomicAdd(&g_cnt[cur_g], cnt);              \
        acc0 = 0; acc1 = 0; cnt = 0.0f;                            \
    } while (0)

    // packed pair: nodes at xr[i0*5+k], xr[(i0+1)*5+k]
#define P1_PAIR(i0) do {                                           \
        ull h0 = b0d, h1 = b1d;                                    \
        _Pragma("unroll")                                          \
        for (int k = 0; k < NODE_F; k++) {                         \
            ull xp = pk2(xr[(i0) * NODE_F + k],                    \
                         xr[(i0 + 1) * NODE_F + k]);               \
            fma2(h0, xp, w0d[k]);                                  \
            fma2(h1, xp, w1d[k]);                                  \
        }                                                          \
        relu2(h0); relu2(h1);                                      \
        acc0 = add2(acc0, h0);                                     \
        acc1 = add2(acc1, h1);                                     \
    } while (0)

    // scalar single node (slow path at segment boundaries)
#define P1_ONE(i) do {                                             \
        float h0 = b0s, h1 = b1s;                                  \
        _Pragma("unroll")                                          \
        for (int k = 0; k < NODE_F; k++) {                         \
            h0 = fmaf(xr[(i) * NODE_F + k], w0s[k], h0);           \
            h1 = fmaf(xr[(i) * NODE_F + k], w1s[k], h1);           \
        }                                                          \
        acc0 = add2(acc0, pk2(fmaxf(h0, 0.0f), 0.0f));             \
        acc1 = add2(acc1, pk2(fmaxf(h1, 0.0f), 0.0f));             \
        cnt += 1.0f;                                               \
    } while (0)

    if (start + NPW <= N) {
        const float4* xv  = (const float4*)(x + start * NODE_F);
        const int4*   bvv = (const int4*)(batch + start);
#pragma unroll 2
        for (int grp = 0; grp < NPW / 4; grp++) {
            int4 bg = __ldg(bvv + grp);
            float4 v0 = __ldg(xv + grp * 5 + 0);
            float4 v1 = __ldg(xv + grp * 5 + 1);
            float4 v2 = __ldg(xv + grp * 5 + 2);
            float4 v3 = __ldg(xv + grp * 5 + 3);
            float4 v4 = __ldg(xv + grp * 5 + 4);
            float xr[20] = { v0.x, v0.y, v0.z, v0.w,
                             v1.x, v1.y, v1.z, v1.w,
                             v2.x, v2.y, v2.z, v2.w,
                             v3.x, v3.y, v3.z, v3.w,
                             v4.x, v4.y, v4.z, v4.w };
            if ((unsigned)bg.w == cur_g) {     // sorted => all 4 in cur_g
                P1_PAIR(0);
                P1_PAIR(2);
                cnt += 4.0f;
            } else {
                int gs[4] = { bg.x, bg.y, bg.z, bg.w };
#pragma unroll
                for (int i = 0; i < 4; i++) {
                    unsigned g = (unsigned)gs[i];
                    if (g >= N_GRAPHS) g = 0;
                    if (g != cur_g) { P1_FLUSH(); cur_g = g; }
                    P1_ONE(i);
                }
            }
        }
    } else {
        long long end = N;
        for (long long n = start; n < end; n++) {
            unsigned g = (unsigned)__ldg(batch + n);
            if (g >= N_GRAPHS) g = 0;
            if (g != cur_g) { P1_FLUSH(); cur_g = g; }
            float xr[NODE_F];
#pragma unroll
            for (int k = 0; k < NODE_F; k++) xr[k] = __ldg(x + n * NODE_F + k);
            P1_ONE(0);
        }
    }
    P1_FLUSH();
#undef P1_ONE
#undef P1_PAIR
#undef P1_FLUSH
}

// ---------------------------------------------------------------------------
// Per-graph: t = aggH@W1b + cnt*b1b ; G = t @ W2a[5:69] + b2a (b2a folded).
// Self-cleaning: zeroes aggH/cnt after consuming so the next graph replay
// starts from a clean accumulator (initial state is the load-time zero-init).
__global__ void k_graph(const float* __restrict__ W1b,
                        const float* __restrict__ b1b,
                        const float* __restrict__ W2a,
                        const float* __restrict__ b2a) {
    int g = blockIdx.x;
    int c = threadIdx.x;          // 64 threads
    __shared__ float sah[HIDDEN];
    __shared__ float t[HIDDEN];
    __shared__ float scnt;

    sah[c] = g_aggH[g * HIDDEN + c];
    if (c == 0) scnt = g_cnt[g];
    __syncthreads();

    // self-clean for next replay
    g_aggH[g * HIDDEN + c] = 0.0f;
    if (c == 0) g_cnt[g] = 0.0f;

    float acc = scnt * __ldg(b1b + c);
#pragma unroll 8
    for (int k = 0; k < HIDDEN; k++)
        acc = fmaf(sah[k], __ldg(W1b + k * HIDDEN + c), acc);
    t[c] = acc;
    __syncthreads();

    float gacc = __ldg(b2a + c);
#pragma unroll 8
    for (int k = 0; k < HIDDEN; k++)
        gacc = fmaf(t[k], __ldg(W2a + (NODE_F + k) * HIDDEN + c), gacc);
    g_G[g * HIDDEN + c] = gacc;
}

// ---------------------------------------------------------------------------
// Pass 2 (channel-major, node-pair packed): thread owns nodes (A,B) packed
// into f32x2 lanes. Loop over 64 channels; weights pre-DUPLICATED in smem so
// each weight loads directly as an f32x2 operand (no dup movs):
//   record per channel c, 20 floats, 16B-aligned:
//   [w0,w0, w1,w1, w2,w2, w3,w3, w4,w4, wb0,wb0, wb1,wb1, wb2,wb2, wb3,wb3, pad,pad]
// Per channel: h=(G_c^A,G_c^B); 5 fma2; relu; 4 fma2 into packed outs.
// ~40 regs -> 5-6 blocks/SM.
#define P2_THREADS 256
#define P2_NODES   512
#define P2_SGMAX   16

__device__ __forceinline__ void p2_core(
    const ull* __restrict__ xp,
    const float* __restrict__ GA, const float* __restrict__ GB,
    const float* __restrict__ sw,
    ull& o0, ull& o1, ull& o2, ull& o3)
{
#pragma unroll 8
    for (int c = 0; c < HIDDEN; c++) {
        const float* rec = sw + c * 20;
        ulonglong2 q0 = *reinterpret_cast<const ulonglong2*>(rec);      // w0d,w1d
        ulonglong2 q1 = *reinterpret_cast<const ulonglong2*>(rec + 4);  // w2d,w3d
        ulonglong2 q2 = *reinterpret_cast<const ulonglong2*>(rec + 8);  // w4d,wb0d
        ulonglong2 q3 = *reinterpret_cast<const ulonglong2*>(rec + 12); // wb1d,wb2d
        ull        q4 = *reinterpret_cast<const ull*>(rec + 16);        // wb3d

        ull h = pk2(GA[c], GB[c]);
        fma2(h, xp[0], q0.x);
        fma2(h, xp[1], q0.y);
        fma2(h, xp[2], q1.x);
        fma2(h, xp[3], q1.y);
        fma2(h, xp[4], q2.x);
        relu2(h);
        fma2(o0, h, q2.y);
        fma2(o1, h, q3.x);
        fma2(o2, h, q3.y);
        fma2(o3, h, q4);
    }
}

__global__ void __launch_bounds__(P2_THREADS)
k_pass2(const float* __restrict__ x,
        const int* __restrict__ batch,
        const float* __restrict__ W2a,
        const float* __restrict__ W2b,
        const float* __restrict__ b2b,
        float* __restrict__ out,
        int N) {
    __shared__ __align__(16) float sw[HIDDEN * 20];       // 5 KB
    __shared__ __align__(16) float sx[P2_NODES * NODE_F]; // 10 KB
    __shared__ __align__(16) float sG[P2_SGMAX * HIDDEN]; // 4 KB

    const int tid = threadIdx.x;
    const long long base = (long long)blockIdx.x * P2_NODES;
    int nmax = (int)(N - base); if (nmax > P2_NODES) nmax = P2_NODES;

    // stage duplicated weight records
    for (int i = tid; i < HIDDEN * 20; i += P2_THREADS) {
        int c = i / 20, f = i % 20;
        float v = 0.0f;
        if (f < 10)      v = W2a[(f >> 1) * HIDDEN + c];
        else if (f < 18) v = W2b[c * OUT_F + ((f - 10) >> 1)];
        sw[i] = v;
    }

    // stage x (float4 main + scalar tail)
    {
        int nf  = nmax * NODE_F;
        int nf4 = nf >> 2;
        const float4* xs4 = (const float4*)(x + base * NODE_F);
        float4* sx4 = (float4*)sx;
        for (int i = tid; i < nf4; i += P2_THREADS) sx4[i] = __ldg(xs4 + i);
        for (int i = nf4 * 4 + tid; i < nf; i += P2_THREADS) sx[i] = __ldg(x + base * NODE_F + i);
    }

    // graph span + stage G rows
    unsigned g0;
    int rows;
    {
        unsigned ga = (unsigned)__ldg(batch + base);
        unsigned gb = (unsigned)__ldg(batch + base + nmax - 1);
        if (ga >= N_GRAPHS) ga = 0;
        if (gb >= N_GRAPHS) gb = 0;
        g0 = ga;
        int span = (int)gb - (int)ga + 1;
        rows = span < 1 ? 1 : (span > P2_SGMAX ? P2_SGMAX : span);
    }
    if (tid < rows * (HIDDEN / 4)) {
        ((float4*)sG)[tid] = __ldg((const float4*)(g_G + (long long)g0 * HIDDEN) + tid);
    }
    __syncthreads();

    const long long nA = base + tid;
    const long long nB = base + tid + P2_THREADS;
    if (nA >= N) return;
    const bool hasB = (nB < N);

    unsigned gA = (unsigned)__ldg(batch + nA);
    if (gA >= N_GRAPHS) gA = 0;
    unsigned gB = gA;
    if (hasB) {
        gB = (unsigned)__ldg(batch + nB);
        if (gB >= N_GRAPHS) gB = 0;
    }
    unsigned relA = gA - g0;
    unsigned relB = gB - g0;

    // pack x pairs (B aliases A when absent)
    ull xp[NODE_F];
    {
        const float* xa = sx + tid * NODE_F;
        const float* xb = hasB ? sx + (tid + P2_THREADS) * NODE_F : xa;
#pragma unroll
        for (int k = 0; k < NODE_F; k++) xp[k] = pk2(xa[k], xb[k]);
    }

    ull o0 = 0, o1 = 0, o2 = 0, o3 = 0;

    if (relA < (unsigned)rows && relB < (unsigned)rows) {
        p2_core(xp, sG + relA * HIDDEN, sG + relB * HIDDEN, sw, o0, o1, o2, o3);
    } else {
        p2_core(xp, g_G + (long long)gA * HIDDEN,
                    g_G + (long long)gB * HIDDEN, sw, o0, o1, o2, o3);
    }

    float4 bb = __ldg((const float4*)b2b);
    float a, b;
    float4 oA, oB;
    upk2(o0, a, b); oA.x = a + bb.x; oB.x = b + bb.x;
    upk2(o1, a, b); oA.y = a + bb.y; oB.y = b + bb.y;
    upk2(o2, a, b); oA.z = a + bb.z; oB.z = b + bb.z;
    upk2(o3, a, b); oA.w = a + bb.w; oB.w = b + bb.w;

    ((float4*)out)[nA] = oA;
    if (hasB) ((float4*)out)[nB] = oB;
}

// ---------------------------------------------------------------------------
extern "C" void kernel_launch(void* const* d_in, const int* in_sizes, int n_in,
                              void* d_out, int out_size) {
    const float* x     = (const float*)d_in[0];
    const int*   batch = (const int*)d_in[2];     // int32 (JAX x64 disabled)
    int wb = n_in - 8;
    const float* W1a = (const float*)d_in[wb + 0];
    const float* b1a = (const float*)d_in[wb + 1];
    const float* W1b = (const float*)d_in[wb + 2];
    const float* b1b = (const float*)d_in[wb + 3];
    const float* W2a = (const float*)d_in[wb + 4];
    const float* b2a = (const float*)d_in[wb + 5];
    const float* W2b = (const float*)d_in[wb + 6];
    const float* b2b = (const float*)d_in[wb + 7];
    float* out = (float*)d_out;

    int N = in_sizes[0] / NODE_F;

    // K1: pass 1 (segment-summed hidden h). aggH/cnt start zero (load-time
    // init for call 1; k_graph self-clean for every subsequent call).
    {
        long long warps = ((long long)N + NPW - 1) / NPW;
        int blocks = (int)((warps * 32 + 255) / 256);
        k_pass1<<<blocks, 256>>>(x, batch, W1a, b1a, N);
    }

    // K2: per-graph GEMMs (b2a folded into G); self-cleans aggH/cnt.
    k_graph<<<N_GRAPHS, HIDDEN>>>(W1b, b1b, W2a, b2a);

    // K3: pass 2 (output)
    {
        int blocks = (int)(((long long)N + P2_NODES - 1) / P2_NODES);
        k_pass2<<<blocks, P2_THREADS>>>(x, batch, W2a, W2b, b2b, out, N);
    }
}

// round 15
// speedup vs baseline: 1.1461x; 1.1461x over previous
#include <cuda_runtime.h>
#include <cuda_bf16.h>

// ---------------------------------------------------------------------------
// mlp_forward_model_44495861187262
//
// restructured (segment_sum distributes over the linear layer):
//   aggH   = segment_sum(relu(x@W1a+b1a))            (pass 1: 5x64 per node)
//   agg    = aggH @ W1b + cnt*b1b                    (per graph)
//   G      = agg @ W2a[5:69]                         (per graph)
//   out    = relu(x@W2a[0:5] + G[batch] + b2a) @ W2b + b2b   (pass 2)
//
// batch is int32 (JAX x64 disabled). edge_index is dead in the reference.
//
// R14 = assembly of measured-best components:
//   pass2 : R7 verbatim (2 nodes/thread, 256 thr / 512 nodes, serial fma
//           chain, b2a in weight record)            -> 38.2 us measured
//   pass1 : R8 pair-packed f32x2                    -> part of rest=29.0 us
//   k_graph: smem-staged aggH (R8), NO b2a fold (matches R7 pass2 contract)
//   k_zero : kept (present in both reference configs)
// ---------------------------------------------------------------------------

#define N_GRAPHS 4096
#define HIDDEN   64
#define NODE_F   5
#define OUT_F    4

typedef unsigned long long ull;

// scratch (allocation-free rule: __device__ globals)
__device__ float g_aggH[N_GRAPHS * HIDDEN];
__device__ float g_cnt[N_GRAPHS];
__device__ float g_G[N_GRAPHS * HIDDEN];

// ---- f32x2 helpers ---------------------------------------------------------
__device__ __forceinline__ ull pk2(float lo, float hi) {
    ull r; asm("mov.b64 %0, {%1,%2};" : "=l"(r) : "f"(lo), "f"(hi)); return r;
}
__device__ __forceinline__ ull pkdup(float v) {
    ull r; asm("mov.b64 %0, {%1,%1};" : "=l"(r) : "f"(v)); return r;
}
__device__ __forceinline__ void upk2(ull v, float& lo, float& hi) {
    asm("mov.b64 {%0,%1}, %2;" : "=f"(lo), "=f"(hi) : "l"(v));
}
__device__ __forceinline__ void fma2(ull& d, ull a, ull b) {
    asm("fma.rn.f32x2 %0, %1, %2, %0;" : "+l"(d) : "l"(a), "l"(b));
}
__device__ __forceinline__ ull add2(ull a, ull b) {
    ull r; asm("add.rn.f32x2 %0, %1, %2;" : "=l"(r) : "l"(a), "l"(b)); return r;
}
__device__ __forceinline__ void relu2(ull& a) {
    float lo, hi; upk2(a, lo, hi);
    lo = fmaxf(lo, 0.0f); hi = fmaxf(hi, 0.0f);
    a = pk2(lo, hi);
}

// ---------------------------------------------------------------------------
__global__ void k_zero() {
    int i = blockIdx.x * blockDim.x + threadIdx.x;
    if (i < N_GRAPHS * HIDDEN) g_aggH[i] = 0.0f;
    if (i < N_GRAPHS)          g_cnt[i]  = 0.0f;
}

// ---------------------------------------------------------------------------
// Pass 1 (R8): warp owns 64 contiguous nodes. Lane owns channels c0=lane,
// c1=lane+32. Nodes processed in PAIRS packed into f32x2 lanes:
// xp[k]=(x_n[k], x_{n+1}[k]); accumulators stay packed (halves summed only at
// flush). batch sorted => graph id warp-uniform; atomic flush only at
// segment boundaries.
#define NPW 64

__global__ void k_pass1(const float* __restrict__ x,
                        const int* __restrict__ batch,
                        const float* __restrict__ W1a,
                        const float* __restrict__ b1a,
                        int N) {
    int warp = (blockIdx.x * blockDim.x + threadIdx.x) >> 5;
    int lane = threadIdx.x & 31;
    long long start = (long long)warp * NPW;
    if (start >= N) return;

    const int c0 = lane, c1 = lane + 32;

    float w0s[NODE_F], w1s[NODE_F];
    ull   w0d[NODE_F], w1d[NODE_F];
#pragma unroll
    for (int k = 0; k < NODE_F; k++) {
        w0s[k] = __ldg(W1a + k * HIDDEN + c0);
        w1s[k] = __ldg(W1a + k * HIDDEN + c1);
        w0d[k] = pkdup(w0s[k]);
        w1d[k] = pkdup(w1s[k]);
    }
    const float b0s = __ldg(b1a + c0);
    const float b1s = __ldg(b1a + c1);
    const ull   b0d = pkdup(b0s);
    const ull   b1d = pkdup(b1s);

    unsigned cur_g;
    {
        unsigned g = (unsigned)__ldg(batch + start);
        cur_g = (g < N_GRAPHS) ? g : 0u;
    }
    ull acc0 = 0, acc1 = 0;
    float cnt = 0.0f;

#define P1_FLUSH() do {                                            \
        float lo, hi;                                              \
        upk2(acc0, lo, hi);                                        \
        atomicAdd(&g_aggH[cur_g * HIDDEN + c0], lo + hi);          \
        upk2(acc1, lo, hi);                                        \
        atomicAdd(&g_aggH[cur_g * HIDDEN + c1], lo + hi);          \
        if (lane == 0) atomicAdd(&g_cnt[cur_g], cnt);              \
        acc0 = 0; acc1 = 0; cnt = 0.0f;                            \
    } while (0)

#define P1_PAIR(i0) do {                                           \
        ull h0 = b0d, h1 = b1d;                                    \
        _Pragma("unroll")                                          \
        for (int k = 0; k < NODE_F; k++) {                         \
            ull xp = pk2(xr[(i0) * NODE_F + k],                    \
                         xr[(i0 + 1) * NODE_F + k]);               \
            fma2(h0, xp, w0d[k]);                                  \
            fma2(h1, xp, w1d[k]);                                  \
        }                                                          \
        relu2(h0); relu2(h1);                                      \
        acc0 = add2(acc0, h0);                                     \
        acc1 = add2(acc1, h1);                                     \
    } while (0)

#define P1_ONE(i) do {                                             \
        float h0 = b0s, h1 = b1s;                                  \
        _Pragma("unroll")                                          \
        for (int k = 0; k < NODE_F; k++) {                         \
            h0 = fmaf(xr[(i) * NODE_F + k], w0s[k], h0);           \
            h1 = fmaf(xr[(i) * NODE_F + k], w1s[k], h1);           \
        }                                                          \
        acc0 = add2(acc0, pk2(fmaxf(h0, 0.0f), 0.0f));             \
        acc1 = add2(acc1, pk2(fmaxf(h1, 0.0f), 0.0f));             \
        cnt += 1.0f;                                               \
    } while (0)

    if (start + NPW <= N) {
        const float4* xv  = (const float4*)(x + start * NODE_F);
        const int4*   bvv = (const int4*)(batch + start);
#pragma unroll 2
        for (int grp = 0; grp < NPW / 4; grp++) {
            int4 bg = __ldg(bvv + grp);
            float4 v0 = __ldg(xv + grp * 5 + 0);
            float4 v1 = __ldg(xv + grp * 5 + 1);
            float4 v2 = __ldg(xv + grp * 5 + 2);
            float4 v3 = __ldg(xv + grp * 5 + 3);
            float4 v4 = __ldg(xv + grp * 5 + 4);
            float xr[20] = { v0.x, v0.y, v0.z, v0.w,
                             v1.x, v1.y, v1.z, v1.w,
                             v2.x, v2.y, v2.z, v2.w,
                             v3.x, v3.y, v3.z, v3.w,
                             v4.x, v4.y, v4.z, v4.w };
            if ((unsigned)bg.w == cur_g) {     // sorted => all 4 in cur_g
                P1_PAIR(0);
                P1_PAIR(2);
                cnt += 4.0f;
            } else {
                int gs[4] = { bg.x, bg.y, bg.z, bg.w };
#pragma unroll
                for (int i = 0; i < 4; i++) {
                    unsigned g = (unsigned)gs[i];
                    if (g >= N_GRAPHS) g = 0;
                    if (g != cur_g) { P1_FLUSH(); cur_g = g; }
                    P1_ONE(i);
                }
            }
        }
    } else {
        long long end = N;
        for (long long n = start; n < end; n++) {
            unsigned g = (unsigned)__ldg(batch + n);
            if (g >= N_GRAPHS) g = 0;
            if (g != cur_g) { P1_FLUSH(); cur_g = g; }
            float xr[NODE_F];
#pragma unroll
            for (int k = 0; k < NODE_F; k++) xr[k] = __ldg(x + n * NODE_F + k);
            P1_ONE(0);
        }
    }
    P1_FLUSH();
#undef P1_ONE
#undef P1_PAIR
#undef P1_FLUSH
}

// ---------------------------------------------------------------------------
// Per-graph: t = aggH@W1b + cnt*b1b ; G = t @ W2a[5:69]  (no b2a fold — R7
// pass2 carries b2a in its weight record). aggH row staged in smem.
__global__ void k_graph(const float* __restrict__ W1b,
                        const float* __restrict__ b1b,
                        const float* __restrict__ W2a) {
    int g = blockIdx.x;
    int c = threadIdx.x;          // 64 threads
    __shared__ float sah[HIDDEN];
    __shared__ float t[HIDDEN];
    __shared__ float scnt;

    sah[c] = g_aggH[g * HIDDEN + c];
    if (c == 0) scnt = g_cnt[g];
    __syncthreads();

    float acc = scnt * __ldg(b1b + c);
#pragma unroll 8
    for (int k = 0; k < HIDDEN; k++)
        acc = fmaf(sah[k], __ldg(W1b + k * HIDDEN + c), acc);
    t[c] = acc;
    __syncthreads();

    float gacc = 0.0f;
#pragma unroll 8
    for (int k = 0; k < HIDDEN; k++)
        gacc = fmaf(t[k], __ldg(W2a + (NODE_F + k) * HIDDEN + c), gacc);
    g_G[g * HIDDEN + c] = gacc;
}

// ---------------------------------------------------------------------------
// Pass 2 (R7 verbatim): 2 nodes per thread, 512 nodes per 256-thread block.
// Weight record per channel pair p (channels 2p,2p+1), 20 floats, 16B-aligned:
//   [0:8)  w_k pairs k=0..3   [8:10) w4,b2a pair interleave — see staging —
//   actually R7 layout: q0=w0,w1  q1=w2,w3  q2=wb0,wb1  q3=wb2,wb3  w4 pair,
//   with b2a packed in f1.y position of the original 12-float record.
// Here we keep R7's exact 20-float record: [0:8) w0..w3 pairs, [8:16) wb0..wb3
// pairs, [16:18) w4 pair, [18:20) b2a pair.
// G rows for the block's graph span staged in smem.
#define P2_THREADS 256
#define P2_NODES   512
#define P2_SGMAX   16

__device__ __forceinline__ void p2_pair(
    const float* __restrict__ xsA, const float* __restrict__ xsB,
    const float* __restrict__ GA,  const float* __restrict__ GB,
    const float* __restrict__ swp,
    float4& oA, float4& oB)
{
    ull xpA[NODE_F], xpB[NODE_F];
#pragma unroll
    for (int k = 0; k < NODE_F; k++) { xpA[k] = pkdup(xsA[k]); xpB[k] = pkdup(xsB[k]); }

    ull a0 = 0, a1 = 0, a2 = 0, a3 = 0;   // outA accumulators (packed even/odd)
    ull b0 = 0, b1 = 0, b2 = 0, b3 = 0;   // outB accumulators

#pragma unroll 8
    for (int p = 0; p < HIDDEN / 2; p++) {
        const float* rec = swp + p * 20;
        ulonglong2 q0 = *reinterpret_cast<const ulonglong2*>(rec);      // w0,w1
        ulonglong2 q1 = *reinterpret_cast<const ulonglong2*>(rec + 4);  // w2,w3
        ulonglong2 q2 = *reinterpret_cast<const ulonglong2*>(rec + 8);  // wb0,wb1
        ulonglong2 q3 = *reinterpret_cast<const ulonglong2*>(rec + 12); // wb2,wb3
        ulonglong2 q4 = *reinterpret_cast<const ulonglong2*>(rec + 16); // w4, b2a

        ull hA = add2(*reinterpret_cast<const ull*>(GA + 2 * p), q4.y);
        ull hB = add2(*reinterpret_cast<const ull*>(GB + 2 * p), q4.y);

        fma2(hA, xpA[0], q0.x); fma2(hB, xpB[0], q0.x);
        fma2(hA, xpA[1], q0.y); fma2(hB, xpB[1], q0.y);
        fma2(hA, xpA[2], q1.x); fma2(hB, xpB[2], q1.x);
        fma2(hA, xpA[3], q1.y); fma2(hB, xpB[3], q1.y);
        fma2(hA, xpA[4], q4.x); fma2(hB, xpB[4], q4.x);

        relu2(hA); relu2(hB);

        fma2(a0, hA, q2.x); fma2(b0, hB, q2.x);
        fma2(a1, hA, q2.y); fma2(b1, hB, q2.y);
        fma2(a2, hA, q3.x); fma2(b2, hB, q3.x);
        fma2(a3, hA, q3.y); fma2(b3, hB, q3.y);
    }
    float lo, hi;
    upk2(a0, lo, hi); oA.x = lo + hi;
    upk2(a1, lo, hi); oA.y = lo + hi;
    upk2(a2, lo, hi); oA.z = lo + hi;
    upk2(a3, lo, hi); oA.w = lo + hi;
    upk2(b0, lo, hi); oB.x = lo + hi;
    upk2(b1, lo, hi); oB.y = lo + hi;
    upk2(b2, lo, hi); oB.z = lo + hi;
    upk2(b3, lo, hi); oB.w = lo + hi;
}

__global__ void __launch_bounds__(P2_THREADS)
k_pass2(const float* __restrict__ x,
        const int* __restrict__ batch,
        const float* __restrict__ W2a,
        const float* __restrict__ b2a,
        const float* __restrict__ W2b,
        const float* __restrict__ b2b,
        float* __restrict__ out,
        int N) {
    __shared__ __align__(16) float sw[(HIDDEN / 2) * 20];
    __shared__ __align__(16) float sx[P2_NODES * NODE_F];
    __shared__ __align__(16) float sG[P2_SGMAX * HIDDEN];

    const int tid = threadIdx.x;
    const long long base = (long long)blockIdx.x * P2_NODES;
    int nmax = (int)(N - base); if (nmax > P2_NODES) nmax = P2_NODES;

    // stage weight records: per channel-pair p (channels 2p, 2p+1):
    // [0:8) w0..w3 pairs  [8:16) wb0..wb3 pairs  [16:18) w4 pair  [18:20) b2a pair
    for (int i = tid; i < (HIDDEN / 2) * 20; i += P2_THREADS) {
        int p = i / 20, f = i % 20;
        float v = 0.0f;
        int ch = 2 * p + (f & 1);
        if (f < 8)       v = W2a[(f >> 1) * HIDDEN + ch];
        else if (f < 16) v = W2b[ch * OUT_F + ((f - 8) >> 1)];
        else if (f < 18) v = W2a[4 * HIDDEN + ch];
        else             v = b2a[ch];
        sw[i] = v;
    }

    // stage x (float4 main + scalar tail)
    {
        int nf  = nmax * NODE_F;
        int nf4 = nf >> 2;
        const float4* xs4 = (const float4*)(x + base * NODE_F);
        float4* sx4 = (float4*)sx;
        for (int i = tid; i < nf4; i += P2_THREADS) sx4[i] = __ldg(xs4 + i);
        for (int i = nf4 * 4 + tid; i < nf; i += P2_THREADS) sx[i] = __ldg(x + base * NODE_F + i);
    }

    // graph span + stage G rows
    unsigned g0;
    int rows;
    {
        unsigned ga = (unsigned)__ldg(batch + base);
        unsigned gb = (unsigned)__ldg(batch + base + nmax - 1);
        if (ga >= N_GRAPHS) ga = 0;
        if (gb >= N_GRAPHS) gb = 0;
        g0 = ga;
        int span = (int)gb - (int)ga + 1;
        rows = span < 1 ? 1 : (span > P2_SGMAX ? P2_SGMAX : span);
    }
    if (tid < rows * (HIDDEN / 4)) {
        ((float4*)sG)[tid] = __ldg((const float4*)(g_G + (long long)g0 * HIDDEN) + tid);
    }
    __syncthreads();

    const long long nA = base + tid;
    const long long nB = base + tid + P2_THREADS;
    if (nA >= N) return;

    float4 bb = __ldg((const float4*)b2b);

    unsigned gA = (unsigned)__ldg(batch + nA);
    if (gA >= N_GRAPHS) gA = 0;
    unsigned relA = gA - g0;

    const float* xsA = sx + tid * NODE_F;
    float4 oA, oB;

    if (nB < N) {
        unsigned gB = (unsigned)__ldg(batch + nB);
        if (gB >= N_GRAPHS) gB = 0;
        unsigned relB = gB - g0;
        const float* xsB = sx + (tid + P2_THREADS) * NODE_F;

        if (relA < (unsigned)rows && relB < (unsigned)rows) {
            p2_pair(xsA, xsB, sG + relA * HIDDEN, sG + relB * HIDDEN, sw, oA, oB);
        } else {
            p2_pair(xsA, xsB, g_G + (long long)gA * HIDDEN,
                              g_G + (long long)gB * HIDDEN, sw, oA, oB);
        }
        oA.x += bb.x; oA.y += bb.y; oA.z += bb.z; oA.w += bb.w;
        oB.x += bb.x; oB.y += bb.y; oB.z += bb.z; oB.w += bb.w;
        ((float4*)out)[nA] = oA;
        ((float4*)out)[nB] = oB;
    } else {
        if (relA < (unsigned)rows) {
            p2_pair(xsA, xsA, sG + relA * HIDDEN, sG + relA * HIDDEN, sw, oA, oB);
        } else {
            p2_pair(xsA, xsA, g_G + (long long)gA * HIDDEN,
                              g_G + (long long)gA * HIDDEN, sw, oA, oB);
        }
        oA.x += bb.x; oA.y += bb.y; oA.z += bb.z; oA.w += bb.w;
        ((float4*)out)[nA] = oA;
    }
}

// ---------------------------------------------------------------------------
extern "C" void kernel_launch(void* const* d_in, const int* in_sizes, int n_in,
                              void* d_out, int out_size) {
    const float* x     = (const float*)d_in[0];
    const int*   batch = (const int*)d_in[2];     // int32 (JAX x64 disabled)
    int wb = n_in - 8;
    const float* W1a = (const float*)d_in[wb + 0];
    const float* b1a = (const float*)d_in[wb + 1];
    const float* W1b = (const float*)d_in[wb + 2];
    const float* b1b = (const float*)d_in[wb + 3];
    const float* W2a = (const float*)d_in[wb + 4];
    const float* b2a = (const float*)d_in[wb + 5];
    const float* W2b = (const float*)d_in[wb + 6];
    const float* b2b = (const float*)d_in[wb + 7];
    float* out = (float*)d_out;

    int N = in_sizes[0] / NODE_F;

    // K0: zero scratch
    k_zero<<<(N_GRAPHS * HIDDEN + 255) / 256, 256>>>();

    // K1: pass 1 (segment-summed hidden h)
    {
        long long warps = ((long long)N + NPW - 1) / NPW;
        int blocks = (int)((warps * 32 + 255) / 256);
        k_pass1<<<blocks, 256>>>(x, batch, W1a, b1a, N);
    }

    // K2: per-graph GEMMs
    k_graph<<<N_GRAPHS, HIDDEN>>>(W1b, b1b, W2a);

    // K3: pass 2 (output)
    {
        int blocks = (int)(((long long)N + P2_NODES - 1) / P2_NODES);
        k_pass2<<<blocks, P2_THREADS>>>(x, batch, W2a, b2a, W2b, b2b, out, N);
    }
}